// round 4
// baseline (speedup 1.0000x reference)
#include <cuda_runtime.h>
#include <cuda_bf16.h>

// TargetedDropout inference path:
//   per channel c (last axis, C=1024), threshold = 16383-th smallest |x| over
//   the N=32768 leading entries; out = (|x| <= thr[c]) ? 0 : x.
//
// Strategy: statistical-window candidate collection (|x| in [0.64,0.71],
// 8-sigma safe for N(0,1) sample median) + exact in-window selection, with an
// always-correct byte-wise radix-select fallback per column.

#define C_DIM   1024
#define N_ROWS  32768
#define RANK0   16383          // int(0.5 * 32768) - 1
#define W_LO    0.64f
#define W_HI    0.71f
#define CAP     2048           // per-column candidate capacity (mean 1457, sd 37)
#define SMALLC  288            // bin-mate capacity in select

__device__ int       g_cnt_below[C_DIM];
__device__ int       g_cand_cnt[C_DIM];
__device__ unsigned  g_cand[CAP * C_DIM];          // layout [pos][col], 8 MB .bss
__device__ __align__(16) float g_thr[C_DIM];

// -------------------------------------------------------------------------
// Pass 0: zero the per-call counters (graph replays must be deterministic)
// -------------------------------------------------------------------------
__global__ void k_zero() {
    int i = threadIdx.x;
    if (i < C_DIM) { g_cnt_below[i] = 0; g_cand_cnt[i] = 0; }
}

// -------------------------------------------------------------------------
// Pass 1: one full read of x. Thread t always owns columns 4t..4t+3 (a float4
// row chunk), so below-counts accumulate in registers. In-window values are
// appended to global candidate scratch.
// grid = 1024 blocks x 256 threads; each block covers 32 rows.
// -------------------------------------------------------------------------
__global__ void __launch_bounds__(256) k_collect(const float4* __restrict__ x) {
    const int t    = threadIdx.x;
    const int col0 = t * 4;
    const int row0 = blockIdx.x * 32;

    int c0 = 0, c1 = 0, c2 = 0, c3 = 0;

    for (int j = 0; j < 32; ++j) {
        float4 v = x[(row0 + j) * 256 + t];
        float a;

        a = fabsf(v.x);
        if (a < W_LO) c0++;
        else if (a <= W_HI) {
            int p = atomicAdd(&g_cand_cnt[col0 + 0], 1);
            if (p < CAP) g_cand[p * C_DIM + col0 + 0] = __float_as_uint(a);
        }
        a = fabsf(v.y);
        if (a < W_LO) c1++;
        else if (a <= W_HI) {
            int p = atomicAdd(&g_cand_cnt[col0 + 1], 1);
            if (p < CAP) g_cand[p * C_DIM + col0 + 1] = __float_as_uint(a);
        }
        a = fabsf(v.z);
        if (a < W_LO) c2++;
        else if (a <= W_HI) {
            int p = atomicAdd(&g_cand_cnt[col0 + 2], 1);
            if (p < CAP) g_cand[p * C_DIM + col0 + 2] = __float_as_uint(a);
        }
        a = fabsf(v.w);
        if (a < W_LO) c3++;
        else if (a <= W_HI) {
            int p = atomicAdd(&g_cand_cnt[col0 + 3], 1);
            if (p < CAP) g_cand[p * C_DIM + col0 + 3] = __float_as_uint(a);
        }
    }

    if (c0) atomicAdd(&g_cnt_below[col0 + 0], c0);
    if (c1) atomicAdd(&g_cnt_below[col0 + 1], c1);
    if (c2) atomicAdd(&g_cnt_below[col0 + 2], c2);
    if (c3) atomicAdd(&g_cnt_below[col0 + 3], c3);
}

// -------------------------------------------------------------------------
// Pass 2: one block per column. Main path: all candidates share exponent 126
// (window subset of [0.5,1)), so a 4096-bin histogram on mantissa bits [22:11]
// plus an exact resolve among bin-mates yields the exact k-th |x| value.
// Fallback (rank outside window / any cap overflow): exact 4-pass byte-wise
// MSD radix select over the raw column from global memory.
// -------------------------------------------------------------------------
__global__ void __launch_bounds__(256) k_select(const float* __restrict__ x) {
    __shared__ unsigned sdata[CAP];     //  8 KB
    __shared__ int      hist[4096];     // 16 KB (fallback reuses first 256)
    __shared__ int      seg[256];
    __shared__ unsigned ssmall[SMALLC];
    __shared__ int      s_smallcnt;
    __shared__ int      s_fb;
    __shared__ int      s_bin, s_r2;
    __shared__ unsigned s_prefix;
    __shared__ int      s_rank;

    const int c = blockIdx.x;
    const int t = threadIdx.x;

    const int n     = g_cand_cnt[c];
    const int below = g_cnt_below[c];
    const int r     = RANK0 - below;

    if (t == 0) {
        s_fb = (n > CAP || r < 0 || r >= n) ? 1 : 0;
        s_smallcnt = 0;
    }
    __syncthreads();

    if (!s_fb) {
        for (int i = t; i < n; i += 256) sdata[i] = g_cand[i * C_DIM + c];
        for (int i = t; i < 4096; i += 256) hist[i] = 0;
        __syncthreads();

        for (int i = t; i < n; i += 256)
            atomicAdd(&hist[(sdata[i] >> 11) & 0xFFF], 1);
        __syncthreads();

        // segmented prefix scan: 256 segments of 16 bins
        int s = 0;
        #pragma unroll
        for (int u = 0; u < 16; ++u) s += hist[t * 16 + u];
        seg[t] = s;
        __syncthreads();

        if (t == 0) {
            int cum = 0, si = 0;
            while (cum + seg[si] <= r) { cum += seg[si]; ++si; }
            int b = si * 16;
            while (cum + hist[b] <= r) { cum += hist[b]; ++b; }
            s_bin = b;
            s_r2  = r - cum;
        }
        __syncthreads();

        const unsigned bsel = (unsigned)s_bin;
        for (int i = t; i < n; i += 256) {
            if (((sdata[i] >> 11) & 0xFFF) == bsel) {
                int p = atomicAdd(&s_smallcnt, 1);
                if (p < SMALLC) ssmall[p] = sdata[i];
            }
        }
        __syncthreads();

        if (t == 0) {
            int m = s_smallcnt;
            if (m > SMALLC) {
                s_fb = 1;                      // pathological: redo exactly
            } else {
                const int r2 = s_r2;
                unsigned ans = 0;
                for (int i = 0; i < m; ++i) {
                    unsigned v = ssmall[i];
                    int less = 0, eq = 0;
                    for (int j = 0; j < m; ++j) {
                        less += (ssmall[j] < v);
                        eq   += (ssmall[j] == v);
                    }
                    if (less <= r2 && r2 < less + eq) { ans = v; break; }
                }
                g_thr[c] = __uint_as_float(ans);
            }
        }
        __syncthreads();
    }

    if (s_fb) {
        // Exact MSD radix select over the whole column (4 x 8-bit passes).
        if (t == 0) { s_prefix = 0; s_rank = RANK0; }
        for (int shift = 24; shift >= 0; shift -= 8) {
            hist[t] = 0;                       // only 256 bins used here
            __syncthreads();
            const unsigned pfx = s_prefix;
            const int hs = shift + 8;
            for (int row = t; row < N_ROWS; row += 256) {
                unsigned key = __float_as_uint(fabsf(x[row * C_DIM + c]));
                bool ok = (hs >= 32) || ((key >> hs) == (pfx >> hs));
                if (ok) atomicAdd(&hist[(key >> shift) & 255], 1);
            }
            __syncthreads();
            if (t == 0) {
                int cum = 0, b = 0;
                while (cum + hist[b] <= s_rank) { cum += hist[b]; ++b; }
                s_rank  -= cum;
                s_prefix |= ((unsigned)b) << shift;
            }
            __syncthreads();
        }
        if (t == 0) g_thr[c] = __uint_as_float(s_prefix);
    }
}

// -------------------------------------------------------------------------
// Pass 3: streaming mask. blockDim must be 256 so each thread's column group
// (threadIdx.x) is loop-invariant -> threshold float4 hoisted out of the loop.
// -------------------------------------------------------------------------
__global__ void __launch_bounds__(256) k_mask(const float4* __restrict__ x,
                                              float4* __restrict__ out,
                                              int n4) {
    const float4 thr = reinterpret_cast<const float4*>(g_thr)[threadIdx.x];
    const int stride = gridDim.x * blockDim.x;   // multiple of 256
    for (int i = blockIdx.x * blockDim.x + threadIdx.x; i < n4; i += stride) {
        float4 v = x[i];
        float4 o;
        o.x = (fabsf(v.x) <= thr.x) ? 0.0f : v.x;
        o.y = (fabsf(v.y) <= thr.y) ? 0.0f : v.y;
        o.z = (fabsf(v.z) <= thr.z) ? 0.0f : v.z;
        o.w = (fabsf(v.w) <= thr.w) ? 0.0f : v.w;
        out[i] = o;
    }
}

extern "C" void kernel_launch(void* const* d_in, const int* in_sizes, int n_in,
                              void* d_out, int out_size) {
    const float* x  = (const float*)d_in[0];
    float* out      = (float*)d_out;
    const int n4    = out_size / 4;              // 8,388,608 float4s

    k_zero   <<<1, 1024>>>();
    k_collect<<<1024, 256>>>((const float4*)x);
    k_select <<<1024, 256>>>(x);
    k_mask   <<<4096, 256>>>((const float4*)x, (float4*)out, n4);
}

// round 5
// speedup vs baseline: 1.0011x; 1.0011x over previous
#include <cuda_runtime.h>
#include <cuda_bf16.h>

// TargetedDropout inference path:
//   per channel c (last axis, C=1024), threshold = 16383-th smallest |x| over
//   the N=32768 leading entries; out = (|x| <= thr[c]) ? 0 : x.
//
// Strategy: statistical-window candidate collection (|x| in [0.64,0.71],
// 8-sigma safe for N(0,1) sample median) + exact in-window selection, with an
// always-correct byte-wise radix-select fallback per column.

#define C_DIM   1024
#define N_ROWS  32768
#define RANK0   16383          // int(0.5 * 32768) - 1
#define W_LO    0.64f
#define W_HI    0.71f
#define CAP     2048           // per-column candidate capacity (mean 1457, sd 37)
#define SMALLC  288            // bin-mate capacity in select

__device__ int       g_cnt_below[C_DIM];
__device__ int       g_cand_cnt[C_DIM];
__device__ unsigned  g_cand[CAP * C_DIM];          // layout [pos][col], 8 MB .bss
__device__ __align__(16) float g_thr[C_DIM];

// -------------------------------------------------------------------------
// Pass 0: zero the per-call counters (graph replays must be deterministic)
// -------------------------------------------------------------------------
__global__ void k_zero() {
    int i = threadIdx.x;
    if (i < C_DIM) { g_cnt_below[i] = 0; g_cand_cnt[i] = 0; }
}

// -------------------------------------------------------------------------
// Pass 1: one full read of x. Thread t always owns columns 4t..4t+3 (a float4
// row chunk), so below-counts accumulate in registers. In-window values are
// appended to global candidate scratch.
// grid = 1024 blocks x 256 threads; each block covers 32 rows.
// -------------------------------------------------------------------------
__global__ void __launch_bounds__(256) k_collect(const float4* __restrict__ x) {
    const int t    = threadIdx.x;
    const int col0 = t * 4;
    const int row0 = blockIdx.x * 32;

    int c0 = 0, c1 = 0, c2 = 0, c3 = 0;

    for (int j = 0; j < 32; ++j) {
        float4 v = x[(row0 + j) * 256 + t];
        float a;

        a = fabsf(v.x);
        if (a < W_LO) c0++;
        else if (a <= W_HI) {
            int p = atomicAdd(&g_cand_cnt[col0 + 0], 1);
            if (p < CAP) g_cand[p * C_DIM + col0 + 0] = __float_as_uint(a);
        }
        a = fabsf(v.y);
        if (a < W_LO) c1++;
        else if (a <= W_HI) {
            int p = atomicAdd(&g_cand_cnt[col0 + 1], 1);
            if (p < CAP) g_cand[p * C_DIM + col0 + 1] = __float_as_uint(a);
        }
        a = fabsf(v.z);
        if (a < W_LO) c2++;
        else if (a <= W_HI) {
            int p = atomicAdd(&g_cand_cnt[col0 + 2], 1);
            if (p < CAP) g_cand[p * C_DIM + col0 + 2] = __float_as_uint(a);
        }
        a = fabsf(v.w);
        if (a < W_LO) c3++;
        else if (a <= W_HI) {
            int p = atomicAdd(&g_cand_cnt[col0 + 3], 1);
            if (p < CAP) g_cand[p * C_DIM + col0 + 3] = __float_as_uint(a);
        }
    }

    if (c0) atomicAdd(&g_cnt_below[col0 + 0], c0);
    if (c1) atomicAdd(&g_cnt_below[col0 + 1], c1);
    if (c2) atomicAdd(&g_cnt_below[col0 + 2], c2);
    if (c3) atomicAdd(&g_cnt_below[col0 + 3], c3);
}

// -------------------------------------------------------------------------
// Pass 2: one block per column. Main path: all candidates share exponent 126
// (window subset of [0.5,1)), so a 4096-bin histogram on mantissa bits [22:11]
// plus an exact resolve among bin-mates yields the exact k-th |x| value.
// Fallback (rank outside window / any cap overflow): exact 4-pass byte-wise
// MSD radix select over the raw column from global memory.
// -------------------------------------------------------------------------
__global__ void __launch_bounds__(256) k_select(const float* __restrict__ x) {
    __shared__ unsigned sdata[CAP];     //  8 KB
    __shared__ int      hist[4096];     // 16 KB (fallback reuses first 256)
    __shared__ int      seg[256];
    __shared__ unsigned ssmall[SMALLC];
    __shared__ int      s_smallcnt;
    __shared__ int      s_fb;
    __shared__ int      s_bin, s_r2;
    __shared__ unsigned s_prefix;
    __shared__ int      s_rank;

    const int c = blockIdx.x;
    const int t = threadIdx.x;

    const int n     = g_cand_cnt[c];
    const int below = g_cnt_below[c];
    const int r     = RANK0 - below;

    if (t == 0) {
        s_fb = (n > CAP || r < 0 || r >= n) ? 1 : 0;
        s_smallcnt = 0;
    }
    __syncthreads();

    if (!s_fb) {
        for (int i = t; i < n; i += 256) sdata[i] = g_cand[i * C_DIM + c];
        for (int i = t; i < 4096; i += 256) hist[i] = 0;
        __syncthreads();

        for (int i = t; i < n; i += 256)
            atomicAdd(&hist[(sdata[i] >> 11) & 0xFFF], 1);
        __syncthreads();

        // segmented prefix scan: 256 segments of 16 bins
        int s = 0;
        #pragma unroll
        for (int u = 0; u < 16; ++u) s += hist[t * 16 + u];
        seg[t] = s;
        __syncthreads();

        if (t == 0) {
            int cum = 0, si = 0;
            while (cum + seg[si] <= r) { cum += seg[si]; ++si; }
            int b = si * 16;
            while (cum + hist[b] <= r) { cum += hist[b]; ++b; }
            s_bin = b;
            s_r2  = r - cum;
        }
        __syncthreads();

        const unsigned bsel = (unsigned)s_bin;
        for (int i = t; i < n; i += 256) {
            if (((sdata[i] >> 11) & 0xFFF) == bsel) {
                int p = atomicAdd(&s_smallcnt, 1);
                if (p < SMALLC) ssmall[p] = sdata[i];
            }
        }
        __syncthreads();

        if (t == 0) {
            int m = s_smallcnt;
            if (m > SMALLC) {
                s_fb = 1;                      // pathological: redo exactly
            } else {
                const int r2 = s_r2;
                unsigned ans = 0;
                for (int i = 0; i < m; ++i) {
                    unsigned v = ssmall[i];
                    int less = 0, eq = 0;
                    for (int j = 0; j < m; ++j) {
                        less += (ssmall[j] < v);
                        eq   += (ssmall[j] == v);
                    }
                    if (less <= r2 && r2 < less + eq) { ans = v; break; }
                }
                g_thr[c] = __uint_as_float(ans);
            }
        }
        __syncthreads();
    }

    if (s_fb) {
        // Exact MSD radix select over the whole column (4 x 8-bit passes).
        if (t == 0) { s_prefix = 0; s_rank = RANK0; }
        for (int shift = 24; shift >= 0; shift -= 8) {
            hist[t] = 0;                       // only 256 bins used here
            __syncthreads();
            const unsigned pfx = s_prefix;
            const int hs = shift + 8;
            for (int row = t; row < N_ROWS; row += 256) {
                unsigned key = __float_as_uint(fabsf(x[row * C_DIM + c]));
                bool ok = (hs >= 32) || ((key >> hs) == (pfx >> hs));
                if (ok) atomicAdd(&hist[(key >> shift) & 255], 1);
            }
            __syncthreads();
            if (t == 0) {
                int cum = 0, b = 0;
                while (cum + hist[b] <= s_rank) { cum += hist[b]; ++b; }
                s_rank  -= cum;
                s_prefix |= ((unsigned)b) << shift;
            }
            __syncthreads();
        }
        if (t == 0) g_thr[c] = __uint_as_float(s_prefix);
    }
}

// -------------------------------------------------------------------------
// Pass 3: streaming mask. blockDim must be 256 so each thread's column group
// (threadIdx.x) is loop-invariant -> threshold float4 hoisted out of the loop.
// -------------------------------------------------------------------------
__global__ void __launch_bounds__(256) k_mask(const float4* __restrict__ x,
                                              float4* __restrict__ out,
                                              int n4) {
    const float4 thr = reinterpret_cast<const float4*>(g_thr)[threadIdx.x];
    const int stride = gridDim.x * blockDim.x;   // multiple of 256
    for (int i = blockIdx.x * blockDim.x + threadIdx.x; i < n4; i += stride) {
        float4 v = x[i];
        float4 o;
        o.x = (fabsf(v.x) <= thr.x) ? 0.0f : v.x;
        o.y = (fabsf(v.y) <= thr.y) ? 0.0f : v.y;
        o.z = (fabsf(v.z) <= thr.z) ? 0.0f : v.z;
        o.w = (fabsf(v.w) <= thr.w) ? 0.0f : v.w;
        out[i] = o;
    }
}

extern "C" void kernel_launch(void* const* d_in, const int* in_sizes, int n_in,
                              void* d_out, int out_size) {
    const float* x  = (const float*)d_in[0];
    float* out      = (float*)d_out;
    const int n4    = out_size / 4;              // 8,388,608 float4s

    k_zero   <<<1, 1024>>>();
    k_collect<<<1024, 256>>>((const float4*)x);
    k_select <<<1024, 256>>>(x);
    k_mask   <<<4096, 256>>>((const float4*)x, (float4*)out, n4);
}

// round 6
// speedup vs baseline: 1.0014x; 1.0003x over previous
#include <cuda_runtime.h>
#include <cuda_bf16.h>

// TargetedDropout inference path:
//   per channel c (last axis, C=1024), threshold = 16383-th smallest |x| over
//   the N=32768 leading entries; out = (|x| <= thr[c]) ? 0 : x.
//
// Strategy: statistical-window candidate collection (|x| in [0.64,0.71],
// 8-sigma safe for N(0,1) sample median) + exact in-window selection, with an
// always-correct byte-wise radix-select fallback per column.

#define C_DIM   1024
#define N_ROWS  32768
#define RANK0   16383          // int(0.5 * 32768) - 1
#define W_LO    0.64f
#define W_HI    0.71f
#define CAP     2048           // per-column candidate capacity (mean 1457, sd 37)
#define SMALLC  288            // bin-mate capacity in select

__device__ int       g_cnt_below[C_DIM];
__device__ int       g_cand_cnt[C_DIM];
__device__ unsigned  g_cand[CAP * C_DIM];          // layout [pos][col], 8 MB .bss
__device__ __align__(16) float g_thr[C_DIM];

// -------------------------------------------------------------------------
// Pass 0: zero the per-call counters (graph replays must be deterministic)
// -------------------------------------------------------------------------
__global__ void k_zero() {
    int i = threadIdx.x;
    if (i < C_DIM) { g_cnt_below[i] = 0; g_cand_cnt[i] = 0; }
}

// -------------------------------------------------------------------------
// Pass 1: one full read of x. Thread t always owns columns 4t..4t+3 (a float4
// row chunk), so below-counts accumulate in registers. In-window values are
// appended to global candidate scratch.
// grid = 1024 blocks x 256 threads; each block covers 32 rows.
// -------------------------------------------------------------------------
__global__ void __launch_bounds__(256) k_collect(const float4* __restrict__ x) {
    const int t    = threadIdx.x;
    const int col0 = t * 4;
    const int row0 = blockIdx.x * 32;

    int c0 = 0, c1 = 0, c2 = 0, c3 = 0;

    for (int j = 0; j < 32; ++j) {
        float4 v = x[(row0 + j) * 256 + t];
        float a;

        a = fabsf(v.x);
        if (a < W_LO) c0++;
        else if (a <= W_HI) {
            int p = atomicAdd(&g_cand_cnt[col0 + 0], 1);
            if (p < CAP) g_cand[p * C_DIM + col0 + 0] = __float_as_uint(a);
        }
        a = fabsf(v.y);
        if (a < W_LO) c1++;
        else if (a <= W_HI) {
            int p = atomicAdd(&g_cand_cnt[col0 + 1], 1);
            if (p < CAP) g_cand[p * C_DIM + col0 + 1] = __float_as_uint(a);
        }
        a = fabsf(v.z);
        if (a < W_LO) c2++;
        else if (a <= W_HI) {
            int p = atomicAdd(&g_cand_cnt[col0 + 2], 1);
            if (p < CAP) g_cand[p * C_DIM + col0 + 2] = __float_as_uint(a);
        }
        a = fabsf(v.w);
        if (a < W_LO) c3++;
        else if (a <= W_HI) {
            int p = atomicAdd(&g_cand_cnt[col0 + 3], 1);
            if (p < CAP) g_cand[p * C_DIM + col0 + 3] = __float_as_uint(a);
        }
    }

    if (c0) atomicAdd(&g_cnt_below[col0 + 0], c0);
    if (c1) atomicAdd(&g_cnt_below[col0 + 1], c1);
    if (c2) atomicAdd(&g_cnt_below[col0 + 2], c2);
    if (c3) atomicAdd(&g_cnt_below[col0 + 3], c3);
}

// -------------------------------------------------------------------------
// Pass 2: one block per column. Main path: all candidates share exponent 126
// (window subset of [0.5,1)), so a 4096-bin histogram on mantissa bits [22:11]
// plus an exact resolve among bin-mates yields the exact k-th |x| value.
// Fallback (rank outside window / any cap overflow): exact 4-pass byte-wise
// MSD radix select over the raw column from global memory.
// -------------------------------------------------------------------------
__global__ void __launch_bounds__(256) k_select(const float* __restrict__ x) {
    __shared__ unsigned sdata[CAP];     //  8 KB
    __shared__ int      hist[4096];     // 16 KB (fallback reuses first 256)
    __shared__ int      seg[256];
    __shared__ unsigned ssmall[SMALLC];
    __shared__ int      s_smallcnt;
    __shared__ int      s_fb;
    __shared__ int      s_bin, s_r2;
    __shared__ unsigned s_prefix;
    __shared__ int      s_rank;

    const int c = blockIdx.x;
    const int t = threadIdx.x;

    const int n     = g_cand_cnt[c];
    const int below = g_cnt_below[c];
    const int r     = RANK0 - below;

    if (t == 0) {
        s_fb = (n > CAP || r < 0 || r >= n) ? 1 : 0;
        s_smallcnt = 0;
    }
    __syncthreads();

    if (!s_fb) {
        for (int i = t; i < n; i += 256) sdata[i] = g_cand[i * C_DIM + c];
        for (int i = t; i < 4096; i += 256) hist[i] = 0;
        __syncthreads();

        for (int i = t; i < n; i += 256)
            atomicAdd(&hist[(sdata[i] >> 11) & 0xFFF], 1);
        __syncthreads();

        // segmented prefix scan: 256 segments of 16 bins
        int s = 0;
        #pragma unroll
        for (int u = 0; u < 16; ++u) s += hist[t * 16 + u];
        seg[t] = s;
        __syncthreads();

        if (t == 0) {
            int cum = 0, si = 0;
            while (cum + seg[si] <= r) { cum += seg[si]; ++si; }
            int b = si * 16;
            while (cum + hist[b] <= r) { cum += hist[b]; ++b; }
            s_bin = b;
            s_r2  = r - cum;
        }
        __syncthreads();

        const unsigned bsel = (unsigned)s_bin;
        for (int i = t; i < n; i += 256) {
            if (((sdata[i] >> 11) & 0xFFF) == bsel) {
                int p = atomicAdd(&s_smallcnt, 1);
                if (p < SMALLC) ssmall[p] = sdata[i];
            }
        }
        __syncthreads();

        if (t == 0) {
            int m = s_smallcnt;
            if (m > SMALLC) {
                s_fb = 1;                      // pathological: redo exactly
            } else {
                const int r2 = s_r2;
                unsigned ans = 0;
                for (int i = 0; i < m; ++i) {
                    unsigned v = ssmall[i];
                    int less = 0, eq = 0;
                    for (int j = 0; j < m; ++j) {
                        less += (ssmall[j] < v);
                        eq   += (ssmall[j] == v);
                    }
                    if (less <= r2 && r2 < less + eq) { ans = v; break; }
                }
                g_thr[c] = __uint_as_float(ans);
            }
        }
        __syncthreads();
    }

    if (s_fb) {
        // Exact MSD radix select over the whole column (4 x 8-bit passes).
        if (t == 0) { s_prefix = 0; s_rank = RANK0; }
        for (int shift = 24; shift >= 0; shift -= 8) {
            hist[t] = 0;                       // only 256 bins used here
            __syncthreads();
            const unsigned pfx = s_prefix;
            const int hs = shift + 8;
            for (int row = t; row < N_ROWS; row += 256) {
                unsigned key = __float_as_uint(fabsf(x[row * C_DIM + c]));
                bool ok = (hs >= 32) || ((key >> hs) == (pfx >> hs));
                if (ok) atomicAdd(&hist[(key >> shift) & 255], 1);
            }
            __syncthreads();
            if (t == 0) {
                int cum = 0, b = 0;
                while (cum + hist[b] <= s_rank) { cum += hist[b]; ++b; }
                s_rank  -= cum;
                s_prefix |= ((unsigned)b) << shift;
            }
            __syncthreads();
        }
        if (t == 0) g_thr[c] = __uint_as_float(s_prefix);
    }
}

// -------------------------------------------------------------------------
// Pass 3: streaming mask. blockDim must be 256 so each thread's column group
// (threadIdx.x) is loop-invariant -> threshold float4 hoisted out of the loop.
// -------------------------------------------------------------------------
__global__ void __launch_bounds__(256) k_mask(const float4* __restrict__ x,
                                              float4* __restrict__ out,
                                              int n4) {
    const float4 thr = reinterpret_cast<const float4*>(g_thr)[threadIdx.x];
    const int stride = gridDim.x * blockDim.x;   // multiple of 256
    for (int i = blockIdx.x * blockDim.x + threadIdx.x; i < n4; i += stride) {
        float4 v = x[i];
        float4 o;
        o.x = (fabsf(v.x) <= thr.x) ? 0.0f : v.x;
        o.y = (fabsf(v.y) <= thr.y) ? 0.0f : v.y;
        o.z = (fabsf(v.z) <= thr.z) ? 0.0f : v.z;
        o.w = (fabsf(v.w) <= thr.w) ? 0.0f : v.w;
        out[i] = o;
    }
}

extern "C" void kernel_launch(void* const* d_in, const int* in_sizes, int n_in,
                              void* d_out, int out_size) {
    const float* x  = (const float*)d_in[0];
    float* out      = (float*)d_out;
    const int n4    = out_size / 4;              // 8,388,608 float4s

    k_zero   <<<1, 1024>>>();
    k_collect<<<1024, 256>>>((const float4*)x);
    k_select <<<1024, 256>>>(x);
    k_mask   <<<4096, 256>>>((const float4*)x, (float4*)out, n4);
}